// round 8
// baseline (speedup 1.0000x reference)
#include <cuda_runtime.h>
#include <cstdint>

// ---------------------------------------------------------------------------
// GCN_35218731827634: 3x (LeakyReLU -> GCNConv). N=100000, E=640000, D=128.
//
// Strategy:
//   once/launch: detect edge dtype + zero deg -> deg -> CSR by dst
//                (scan computes rowptr AND dinv; fill packs (src,w) records)
//   per layer:   h = leaky_relu(X) @ W      (SGEMM w/ register-staged prefetch)
//                out[i] = b + h[i]*dinv[i]^2 + sum_e w_e * h[src_e]
//                          (half-warp/node gather, 4 outstanding LDGs, no atomics)
// g_h (51.2MB) fits in L2 -> the random gather is L2-resident.
// ---------------------------------------------------------------------------

#define N_NODES 100000
#define N_EDGES 640000
#define D 128
#define SCAN_B 1024

struct EdgeRec { int src; float w; };   // 8B packed edge record

// scratch (device globals: no allocation allowed)
__device__ float   g_h[(size_t)N_NODES * D];
__device__ float   g_a[(size_t)N_NODES * D];
__device__ float   g_b[(size_t)N_NODES * D];
__device__ float   g_dinv[N_NODES];
__device__ int     g_deg[N_NODES];
__device__ int     g_rowptr[N_NODES + 1];
__device__ int     g_cursor[N_NODES];
__device__ int     g_blocksum[(N_NODES + SCAN_B - 1) / SCAN_B];
__device__ int     g_blockoff[(N_NODES + SCAN_B - 1) / SCAN_B];
__device__ EdgeRec g_edges[N_EDGES];
__device__ int     g_is64;             // 1 if edge_index is int64, 0 if int32

__device__ __forceinline__ float* sel_buf(int sel, float* ext) {
    return sel == 0 ? ext : (sel == 1 ? g_a : g_b);
}
__device__ __forceinline__ const float* sel_cbuf(int sel, const float* ext) {
    return sel == 0 ? ext : (sel == 1 ? (const float*)g_a : (const float*)g_b);
}

__device__ __forceinline__ int edge_at(const void* ei, size_t idx, int is64) {
    if (is64) return (int)((const long long*)ei)[idx];
    return ((const int*)ei)[idx];
}

// ------------------------- dtype detect + deg zero -------------------------
// int64 indices are < n, so every u64 word is < n. int32 data read as u64 is
// lo | hi<<32 with hi a neighboring index (>= 2^32 unless hi==0, p ~ 1e-5).
// 16 words -> misdetect probability ~1e-80. Reads 128B only (safe either way).
__global__ void init_kernel(const void* ei, int n) {
    int i = blockIdx.x * blockDim.x + threadIdx.x;
    if (i < n) g_deg[i] = 0;
    if (i == 0) {
        const unsigned long long* p = (const unsigned long long*)ei;
        int ok = 1;
        for (int k = 0; k < 16; k++)
            if (p[k] >= (unsigned long long)n) ok = 0;
        g_is64 = ok;
    }
}

// ------------------------------ degree -------------------------------------
__global__ void count_deg_kernel(const void* __restrict__ ei, int E) {
    int e = blockIdx.x * blockDim.x + threadIdx.x;
    if (e < E) {
        int is64 = g_is64;
        atomicAdd(&g_deg[edge_at(ei, (size_t)E + e, is64)], 1);
    }
}

// ------------------------------ CSR build ----------------------------------
// exclusive scan of g_deg -> block-local rowptr + per-block totals.
// Also computes g_dinv here (deg already in a register).
__global__ __launch_bounds__(SCAN_B) void scan_block_kernel(int n) {
    __shared__ int warp_sums[32];
    int i = blockIdx.x * SCAN_B + threadIdx.x;
    int v = (i < n) ? g_deg[i] : 0;
    int lane = threadIdx.x & 31, wid = threadIdx.x >> 5;

    if (i < n) g_dinv[i] = rsqrtf((float)(v + 1));  // +1 self loop

    int s = v;
#pragma unroll
    for (int o = 1; o < 32; o <<= 1) {
        int t = __shfl_up_sync(0xffffffffu, s, o);
        if (lane >= o) s += t;
    }
    if (lane == 31) warp_sums[wid] = s;
    __syncthreads();
    if (wid == 0) {
        int ws = warp_sums[lane];
#pragma unroll
        for (int o = 1; o < 32; o <<= 1) {
            int t = __shfl_up_sync(0xffffffffu, ws, o);
            if (lane >= o) ws += t;
        }
        warp_sums[lane] = ws;
    }
    __syncthreads();
    int excl = s - v + (wid > 0 ? warp_sums[wid - 1] : 0);
    if (i < n) g_rowptr[i] = excl;
    if (threadIdx.x == SCAN_B - 1) g_blocksum[blockIdx.x] = excl + v;
}

__global__ void scan_sums_kernel(int nb, int n) {
    if (threadIdx.x == 0 && blockIdx.x == 0) {
        int acc = 0;
        for (int b = 0; b < nb; b++) {
            int t = g_blocksum[b];
            g_blockoff[b] = acc;
            acc += t;
        }
        g_rowptr[n] = acc;
    }
}

__global__ void finalize_rowptr_kernel(int n) {
    int i = blockIdx.x * blockDim.x + threadIdx.x;
    if (i < n) {
        int r = g_rowptr[i] + g_blockoff[i / SCAN_B];
        g_rowptr[i] = r;
        g_cursor[i] = r;
    }
}

__global__ void fill_csr_kernel(const void* __restrict__ ei, int E) {
    int e = blockIdx.x * blockDim.x + threadIdx.x;
    if (e >= E) return;
    int is64 = g_is64;
    int s = edge_at(ei, e, is64);
    int d = edge_at(ei, (size_t)E + e, is64);
    int pos = atomicAdd(&g_cursor[d], 1);
    EdgeRec r;
    r.src = s;
    r.w = g_dinv[s] * g_dinv[d];
    g_edges[pos] = r;
}

// ------------------------------ GEMM ---------------------------------------
// h = leaky_relu(X) @ W. Tiles TM=64 x TN=128, TK=32; 256 thr, 4x8 microtile.
// Register-staged prefetch: next tile's global loads issue before this tile's
// FMA block, hiding L2/DRAM latency under 1024 FMAs/thread-tile.
#define TM 64
#define TN 128
#define TK 32

__global__ __launch_bounds__(256) void gemm_act_kernel(
    const float* __restrict__ Xext, int xsel,
    const float* __restrict__ W, int n)
{
    const float* X = sel_cbuf(xsel, Xext);

    __shared__ float Xs[TK][TM + 1];
    __shared__ float Ws[TK][TN];

    const int tid = threadIdx.x;
    const int tx = tid & 15;           // col group (8 cols)
    const int ty = tid >> 4;           // row group (4 rows)
    const int row0 = blockIdx.x * TM;

    const int xm0 = tid >> 3;                 // X row within tile (slot 0)
    const int xq0 = tid & 7;                  // X float4-in-k   (slot 0)
    const int xm1 = (tid + 256) >> 3;
    const int xq1 = (tid + 256) & 7;
    const int xr0 = row0 + xm0, xr1 = row0 + xm1;

    float acc[4][8];
#pragma unroll
    for (int i = 0; i < 4; i++)
#pragma unroll
        for (int j = 0; j < 8; j++) acc[i][j] = 0.f;

    // ---- stage tile 0 ----
    float4 vx0 = make_float4(0.f, 0.f, 0.f, 0.f), vx1 = vx0;
    if (xr0 < n) vx0 = *(const float4*)(X + (size_t)xr0 * D + xq0 * 4);
    if (xr1 < n) vx1 = *(const float4*)(X + (size_t)xr1 * D + xq1 * 4);
    float4 vw[4];
#pragma unroll
    for (int r = 0; r < 4; r++) {
        int idx = tid + 256 * r;
        vw[r] = *(const float4*)(W + (size_t)(idx >> 5) * D + (idx & 31) * 4);
    }

    for (int kt = 0; kt < D; kt += TK) {
        // ---- commit staged tile to smem (leaky-relu on X) ----
        {
            float4 v = vx0;
            v.x = v.x > 0.f ? v.x : 0.01f * v.x;
            v.y = v.y > 0.f ? v.y : 0.01f * v.y;
            v.z = v.z > 0.f ? v.z : 0.01f * v.z;
            v.w = v.w > 0.f ? v.w : 0.01f * v.w;
            Xs[xq0 * 4 + 0][xm0] = v.x;
            Xs[xq0 * 4 + 1][xm0] = v.y;
            Xs[xq0 * 4 + 2][xm0] = v.z;
            Xs[xq0 * 4 + 3][xm0] = v.w;
            v = vx1;
            v.x = v.x > 0.f ? v.x : 0.01f * v.x;
            v.y = v.y > 0.f ? v.y : 0.01f * v.y;
            v.z = v.z > 0.f ? v.z : 0.01f * v.z;
            v.w = v.w > 0.f ? v.w : 0.01f * v.w;
            Xs[xq1 * 4 + 0][xm1] = v.x;
            Xs[xq1 * 4 + 1][xm1] = v.y;
            Xs[xq1 * 4 + 2][xm1] = v.z;
            Xs[xq1 * 4 + 3][xm1] = v.w;
#pragma unroll
            for (int r = 0; r < 4; r++) {
                int idx = tid + 256 * r;
                *(float4*)&Ws[idx >> 5][(idx & 31) * 4] = vw[r];
            }
        }
        __syncthreads();

        // ---- stage NEXT tile (overlaps with FMA block below) ----
        int ktn = kt + TK;
        if (ktn < D) {
            vx0 = make_float4(0.f, 0.f, 0.f, 0.f); vx1 = vx0;
            if (xr0 < n) vx0 = *(const float4*)(X + (size_t)xr0 * D + ktn + xq0 * 4);
            if (xr1 < n) vx1 = *(const float4*)(X + (size_t)xr1 * D + ktn + xq1 * 4);
#pragma unroll
            for (int r = 0; r < 4; r++) {
                int idx = tid + 256 * r;
                vw[r] = *(const float4*)(W + (size_t)(ktn + (idx >> 5)) * D + (idx & 31) * 4);
            }
        }

        // ---- FMA block ----
#pragma unroll
        for (int k = 0; k < TK; k++) {
            float a[4], b[8];
#pragma unroll
            for (int i = 0; i < 4; i++) a[i] = Xs[k][ty * 4 + i];
#pragma unroll
            for (int j = 0; j < 8; j++) b[j] = Ws[k][tx * 8 + j];
#pragma unroll
            for (int i = 0; i < 4; i++)
#pragma unroll
                for (int j = 0; j < 8; j++) acc[i][j] = fmaf(a[i], b[j], acc[i][j]);
        }
        __syncthreads();
    }

#pragma unroll
    for (int i = 0; i < 4; i++) {
        int grow = row0 + ty * 4 + i;
        if (grow >= n) continue;
#pragma unroll
        for (int j = 0; j < 8; j += 4) {
            *(float4*)(g_h + (size_t)grow * D + tx * 8 + j) =
                make_float4(acc[i][j], acc[i][j + 1], acc[i][j + 2], acc[i][j + 3]);
        }
    }
}

// ------------------------------ aggregate ----------------------------------
// HALF-WARP (16 lanes) per node: lane covers float4 slots {lane, lane+16}.
// out[i] = bias + h[i]*dinv^2 + sum_e w_e * h[src_e].  No atomics.
// 2-deep edge pipeline x 2 loads/edge -> 4 outstanding LDG.128 per thread.
__global__ __launch_bounds__(256) void aggregate_kernel(
    float* __restrict__ Oext, int osel, const float* __restrict__ bias, int n)
{
    int gid  = blockIdx.x * 256 + threadIdx.x;
    int node = gid >> 4;
    int lane = gid & 15;
    if (node >= n) return;

    float* OUT = sel_buf(osel, Oext);

    int beg = g_rowptr[node];
    int end = g_rowptr[node + 1];
    float di = g_dinv[node];
    float d2 = di * di;

    const int o0 = lane * 4;            // floats 4*lane .. 4*lane+3
    const int o1 = (lane + 16) * 4;     // floats 4*lane+64 ..

    float4 bv0 = *(const float4*)(bias + o0);
    float4 bv1 = *(const float4*)(bias + o1);
    const float* hrow = g_h + (size_t)node * D;
    float4 hv0 = *(const float4*)(hrow + o0);
    float4 hv1 = *(const float4*)(hrow + o1);

    float4 a0, a1;
    a0.x = fmaf(hv0.x, d2, bv0.x);
    a0.y = fmaf(hv0.y, d2, bv0.y);
    a0.z = fmaf(hv0.z, d2, bv0.z);
    a0.w = fmaf(hv0.w, d2, bv0.w);
    a1.x = fmaf(hv1.x, d2, bv1.x);
    a1.y = fmaf(hv1.y, d2, bv1.y);
    a1.z = fmaf(hv1.z, d2, bv1.z);
    a1.w = fmaf(hv1.w, d2, bv1.w);

    int cnt = end - beg;
    if (cnt > 0) {
        const EdgeRec* ep = g_edges + beg;
        EdgeRec e0 = ep[0];
        EdgeRec e1 = (cnt > 1) ? ep[1] : e0;

        int i = 0;
        for (; i + 1 < cnt; i += 2) {
            const float* s0 = g_h + (size_t)e0.src * D;
            const float* s1 = g_h + (size_t)e1.src * D;
            float4 m00 = *(const float4*)(s0 + o0);
            float4 m01 = *(const float4*)(s0 + o1);
            float4 m10 = *(const float4*)(s1 + o0);
            float4 m11 = *(const float4*)(s1 + o1);
            float w0 = e0.w, w1 = e1.w;
            if (i + 2 < cnt) e0 = ep[i + 2];
            if (i + 3 < cnt) e1 = ep[i + 3];
            a0.x = fmaf(w0, m00.x, a0.x);
            a0.y = fmaf(w0, m00.y, a0.y);
            a0.z = fmaf(w0, m00.z, a0.z);
            a0.w = fmaf(w0, m00.w, a0.w);
            a1.x = fmaf(w0, m01.x, a1.x);
            a1.y = fmaf(w0, m01.y, a1.y);
            a1.z = fmaf(w0, m01.z, a1.z);
            a1.w = fmaf(w0, m01.w, a1.w);
            a0.x = fmaf(w1, m10.x, a0.x);
            a0.y = fmaf(w1, m10.y, a0.y);
            a0.z = fmaf(w1, m10.z, a0.z);
            a0.w = fmaf(w1, m10.w, a0.w);
            a1.x = fmaf(w1, m11.x, a1.x);
            a1.y = fmaf(w1, m11.y, a1.y);
            a1.z = fmaf(w1, m11.z, a1.z);
            a1.w = fmaf(w1, m11.w, a1.w);
        }
        if (i < cnt) {
            const float* s0 = g_h + (size_t)e0.src * D;
            float4 m00 = *(const float4*)(s0 + o0);
            float4 m01 = *(const float4*)(s0 + o1);
            a0.x = fmaf(e0.w, m00.x, a0.x);
            a0.y = fmaf(e0.w, m00.y, a0.y);
            a0.z = fmaf(e0.w, m00.z, a0.z);
            a0.w = fmaf(e0.w, m00.w, a0.w);
            a1.x = fmaf(e0.w, m01.x, a1.x);
            a1.y = fmaf(e0.w, m01.y, a1.y);
            a1.z = fmaf(e0.w, m01.z, a1.z);
            a1.w = fmaf(e0.w, m01.w, a1.w);
        }
    }

    float* orow = OUT + (size_t)node * D;
    *(float4*)(orow + o0) = a0;
    *(float4*)(orow + o1) = a1;
}

// ---------------------------------------------------------------------------
extern "C" void kernel_launch(void* const* d_in, const int* in_sizes, int n_in,
                              void* d_out, int out_size)
{
    const float* x  = (const float*)d_in[0];
    const void*  ei = d_in[1];               // int64 or int32, detected on device
    const float* W1 = (const float*)d_in[2];
    const float* b1 = (const float*)d_in[3];
    const float* W2 = (const float*)d_in[4];
    const float* b2 = (const float*)d_in[5];
    const float* W3 = (const float*)d_in[6];
    const float* b3 = (const float*)d_in[7];
    float* out = (float*)d_out;

    const int n = in_sizes[0] / D;       // 100000
    const int E = in_sizes[1] / 2;       // 640000
    const int T = 256;
    const int nb = (n + SCAN_B - 1) / SCAN_B;

    // ---- once per launch: dtype detect + dinv + CSR ----
    init_kernel<<<(n + T - 1) / T, T>>>(ei, n);
    count_deg_kernel<<<(E + T - 1) / T, T>>>(ei, E);
    scan_block_kernel<<<nb, SCAN_B>>>(n);     // also computes g_dinv
    scan_sums_kernel<<<1, 32>>>(nb, n);
    finalize_rowptr_kernel<<<(n + T - 1) / T, T>>>(n);
    fill_csr_kernel<<<(E + T - 1) / T, T>>>(ei, E);

    const int gemm_blocks = (n + TM - 1) / TM;
    const int agg_blocks = (int)(((long long)n * 16 + T - 1) / T);

    // layer 1: x -> g_a
    gemm_act_kernel<<<gemm_blocks, T>>>(x, 0, W1, n);
    aggregate_kernel<<<agg_blocks, T>>>(nullptr, 1, b1, n);

    // layer 2: g_a -> g_b
    gemm_act_kernel<<<gemm_blocks, T>>>(nullptr, 1, W2, n);
    aggregate_kernel<<<agg_blocks, T>>>(nullptr, 2, b2, n);

    // layer 3: g_b -> d_out
    gemm_act_kernel<<<gemm_blocks, T>>>(nullptr, 2, W3, n);
    aggregate_kernel<<<agg_blocks, T>>>(out, 0, b3, n);
}

// round 10
// speedup vs baseline: 1.3124x; 1.3124x over previous
#include <cuda_runtime.h>
#include <cstdint>

// ---------------------------------------------------------------------------
// GCN_35218731827634: 3x (LeakyReLU -> GCNConv). N=100000, E=640000, D=128.
//
// R10 vs 565us baseline:
//  - GEMM mainloop: packed fma.rn.f32x2 (FFMA2), X duplicated {x,x} in smem
//    (A pairs via broadcast LDS.64), B columns PAIR-INTERLEAVED per thread
//    (2tx+32j) so B LDS.64 is bank-conflict-free.
//  - scan_sums serial kernel folded into finalize; setup is 5 launches.
// ---------------------------------------------------------------------------

#define N_NODES 100000
#define N_EDGES 640000
#define D 128
#define SCAN_B 1024

struct EdgeRec { int src; float w; };   // 8B packed edge record

// scratch (device globals: no allocation allowed)
__device__ float   g_h[(size_t)N_NODES * D];
__device__ float   g_a[(size_t)N_NODES * D];
__device__ float   g_b[(size_t)N_NODES * D];
__device__ float   g_dinv[N_NODES];
__device__ int     g_deg[N_NODES];
__device__ int     g_rowptr[N_NODES + 1];
__device__ int     g_cursor[N_NODES];
__device__ int     g_blocksum[(N_NODES + SCAN_B - 1) / SCAN_B];
__device__ EdgeRec g_edges[N_EDGES];
__device__ int     g_is64;             // 1 if edge_index is int64, 0 if int32

__device__ __forceinline__ float* sel_buf(int sel, float* ext) {
    return sel == 0 ? ext : (sel == 1 ? g_a : g_b);
}
__device__ __forceinline__ const float* sel_cbuf(int sel, const float* ext) {
    return sel == 0 ? ext : (sel == 1 ? (const float*)g_a : (const float*)g_b);
}

__device__ __forceinline__ int edge_at(const void* ei, size_t idx, int is64) {
    if (is64) return (int)((const long long*)ei)[idx];
    return ((const int*)ei)[idx];
}

// ------------------------- dtype detect + deg zero -------------------------
__global__ void init_kernel(const void* ei, int n) {
    int i = blockIdx.x * blockDim.x + threadIdx.x;
    if (i < n) g_deg[i] = 0;
    if (i == 0) {
        const unsigned long long* p = (const unsigned long long*)ei;
        int ok = 1;
        for (int k = 0; k < 16; k++)
            if (p[k] >= (unsigned long long)n) ok = 0;
        g_is64 = ok;
    }
}

// ------------------------------ degree -------------------------------------
__global__ void count_deg_kernel(const void* __restrict__ ei, int E) {
    int e = blockIdx.x * blockDim.x + threadIdx.x;
    if (e < E) {
        int is64 = g_is64;
        atomicAdd(&g_deg[edge_at(ei, (size_t)E + e, is64)], 1);
    }
}

// ------------------------------ CSR build ----------------------------------
__global__ __launch_bounds__(SCAN_B) void scan_block_kernel(int n) {
    __shared__ int warp_sums[32];
    int i = blockIdx.x * SCAN_B + threadIdx.x;
    int v = (i < n) ? g_deg[i] : 0;
    int lane = threadIdx.x & 31, wid = threadIdx.x >> 5;

    if (i < n) g_dinv[i] = rsqrtf((float)(v + 1));  // +1 self loop

    int s = v;
#pragma unroll
    for (int o = 1; o < 32; o <<= 1) {
        int t = __shfl_up_sync(0xffffffffu, s, o);
        if (lane >= o) s += t;
    }
    if (lane == 31) warp_sums[wid] = s;
    __syncthreads();
    if (wid == 0) {
        int ws = warp_sums[lane];
#pragma unroll
        for (int o = 1; o < 32; o <<= 1) {
            int t = __shfl_up_sync(0xffffffffu, ws, o);
            if (lane >= o) ws += t;
        }
        warp_sums[lane] = ws;
    }
    __syncthreads();
    int excl = s - v + (wid > 0 ? warp_sums[wid - 1] : 0);
    if (i < n) g_rowptr[i] = excl;
    if (threadIdx.x == SCAN_B - 1) g_blocksum[blockIdx.x] = excl + v;
}

// finalize: add global block offset (per-block tree reduction over blocksums),
// init cursor, rowptr[n]=E.
__global__ __launch_bounds__(256) void finalize_rowptr_kernel(int n, int nb, int E) {
    __shared__ int sh[256];
    int t = threadIdx.x;
    int sb = (blockIdx.x * 256) / SCAN_B;   // 256 | 1024 -> whole block same sb
    sh[t] = (t < sb) ? g_blocksum[t] : 0;
    __syncthreads();
#pragma unroll
    for (int o = 128; o > 0; o >>= 1) {
        if (t < o) sh[t] += sh[t + o];
        __syncthreads();
    }
    int off = sh[0];
    int i = blockIdx.x * 256 + t;
    if (i < n) {
        int r = g_rowptr[i] + off;
        g_rowptr[i] = r;
        g_cursor[i] = r;
    }
    if (i == 0) g_rowptr[n] = E;
}

__global__ void fill_csr_kernel(const void* __restrict__ ei, int E) {
    int e = blockIdx.x * blockDim.x + threadIdx.x;
    if (e >= E) return;
    int is64 = g_is64;
    int s = edge_at(ei, e, is64);
    int d = edge_at(ei, (size_t)E + e, is64);
    int pos = atomicAdd(&g_cursor[d], 1);
    EdgeRec r;
    r.src = s;
    r.w = g_dinv[s] * g_dinv[d];
    g_edges[pos] = r;
}

// ------------------------------ GEMM ---------------------------------------
// h = leaky_relu(X) @ W.  TM=64 x TN=128, TK=32; 256 thr; per thread 4 rows x
// 4 column-PAIRS (pair-interleaved: cols {2tx, 2tx+32, 2tx+64, 2tx+96}).
// FFMA2 mainloop: A pairs broadcast LDS.64 from duplicated Xs; B pairs
// conflict-free LDS.64 (lane byte-stride 8).
#define TM 64
#define TN 128
#define TK 32

__global__ __launch_bounds__(256) void gemm_act_kernel(
    const float* __restrict__ Xext, int xsel,
    const float* __restrict__ W, int n)
{
    const float* X = sel_cbuf(xsel, Xext);

    __shared__ float Xs[TK][2 * TM + 2];   // duplicated pairs {x,x}
    __shared__ float Ws[TK][TN];

    const int tid = threadIdx.x;
    const int tx = tid & 15;           // column-pair group
    const int ty = tid >> 4;           // row group (4 rows)
    const int row0 = blockIdx.x * TM;

    const int xm0 = tid >> 3;                 // X row within tile (slot 0)
    const int xq0 = tid & 7;                  // X float4-in-k   (slot 0)
    const int xm1 = (tid + 256) >> 3;
    const int xq1 = (tid + 256) & 7;
    const int xr0 = row0 + xm0, xr1 = row0 + xm1;

    unsigned long long acc2[4][4];            // [row i][pair j]
#pragma unroll
    for (int i = 0; i < 4; i++)
#pragma unroll
        for (int j = 0; j < 4; j++) acc2[i][j] = 0ull;

    // ---- stage tile 0 ----
    float4 vx0 = make_float4(0.f, 0.f, 0.f, 0.f), vx1 = vx0;
    if (xr0 < n) vx0 = *(const float4*)(X + (size_t)xr0 * D + xq0 * 4);
    if (xr1 < n) vx1 = *(const float4*)(X + (size_t)xr1 * D + xq1 * 4);
    float4 vw[4];
#pragma unroll
    for (int r = 0; r < 4; r++) {
        int idx = tid + 256 * r;
        vw[r] = *(const float4*)(W + (size_t)(idx >> 5) * D + (idx & 31) * 4);
    }

    for (int kt = 0; kt < D; kt += TK) {
        // ---- commit staged tile to smem (leaky-relu on X, duplicated {x,x}) ----
        {
            float c[4];
            c[0] = vx0.x > 0.f ? vx0.x : 0.01f * vx0.x;
            c[1] = vx0.y > 0.f ? vx0.y : 0.01f * vx0.y;
            c[2] = vx0.z > 0.f ? vx0.z : 0.01f * vx0.z;
            c[3] = vx0.w > 0.f ? vx0.w : 0.01f * vx0.w;
#pragma unroll
            for (int q = 0; q < 4; q++)
                *(float2*)&Xs[xq0 * 4 + q][2 * xm0] = make_float2(c[q], c[q]);
            c[0] = vx1.x > 0.f ? vx1.x : 0.01f * vx1.x;
            c[1] = vx1.y > 0.f ? vx1.y : 0.01f * vx1.y;
            c[2] = vx1.z > 0.f ? vx1.z : 0.01f * vx1.z;
            c[3] = vx1.w > 0.f ? vx1.w : 0.01f * vx1.w;
#pragma unroll
            for (int q = 0; q < 4; q++)
                *(float2*)&Xs[xq1 * 4 + q][2 * xm1] = make_float2(c[q], c[q]);
#pragma unroll
            for (int r = 0; r < 4; r++) {
                int idx = tid + 256 * r;
                *(float4*)&Ws[idx >> 5][(idx & 31) * 4] = vw[r];
            }
        }
        __syncthreads();

        // ---- stage NEXT tile (overlaps with FFMA2 block below) ----
        int ktn = kt + TK;
        if (ktn < D) {
            vx0 = make_float4(0.f, 0.f, 0.f, 0.f); vx1 = vx0;
            if (xr0 < n) vx0 = *(const float4*)(X + (size_t)xr0 * D + ktn + xq0 * 4);
            if (xr1 < n) vx1 = *(const float4*)(X + (size_t)xr1 * D + ktn + xq1 * 4);
#pragma unroll
            for (int r = 0; r < 4; r++) {
                int idx = tid + 256 * r;
                vw[r] = *(const float4*)(W + (size_t)(ktn + (idx >> 5)) * D + (idx & 31) * 4);
            }
        }

        // ---- FFMA2 block ----
#pragma unroll
        for (int k = 0; k < TK; k++) {
            unsigned long long A[4], B[4];
#pragma unroll
            for (int i = 0; i < 4; i++)
                A[i] = *(const unsigned long long*)&Xs[k][2 * (ty * 4 + i)];
#pragma unroll
            for (int j = 0; j < 4; j++)
                B[j] = *(const unsigned long long*)&Ws[k][2 * tx + 32 * j];
#pragma unroll
            for (int i = 0; i < 4; i++)
#pragma unroll
                for (int j = 0; j < 4; j++)
                    asm("fma.rn.f32x2 %0, %1, %2, %0;"
                        : "+l"(acc2[i][j]) : "l"(A[i]), "l"(B[j]));
        }
        __syncthreads();
    }

    // ---- epilogue: store 4 float2 per row (coalesced: lane stride 8B) ----
#pragma unroll
    for (int i = 0; i < 4; i++) {
        int grow = row0 + ty * 4 + i;
        if (grow >= n) continue;
        float* hrow = g_h + (size_t)grow * D;
#pragma unroll
        for (int j = 0; j < 4; j++) {
            unsigned lo, hi;
            asm("mov.b64 {%0,%1}, %2;" : "=r"(lo), "=r"(hi) : "l"(acc2[i][j]));
            *(float2*)(hrow + 2 * tx + 32 * j) =
                make_float2(__uint_as_float(lo), __uint_as_float(hi));
        }
    }
}

// ------------------------------ aggregate ----------------------------------
// HALF-WARP (16 lanes) per node: lane covers float4 slots {lane, lane+16}.
// out[i] = bias + h[i]*dinv^2 + sum_e w_e * h[src_e].  No atomics.
__global__ __launch_bounds__(256) void aggregate_kernel(
    float* __restrict__ Oext, int osel, const float* __restrict__ bias, int n)
{
    int gid  = blockIdx.x * 256 + threadIdx.x;
    int node = gid >> 4;
    int lane = gid & 15;
    if (node >= n) return;

    float* OUT = sel_buf(osel, Oext);

    int beg = g_rowptr[node];
    int end = g_rowptr[node + 1];
    float di = g_dinv[node];
    float d2 = di * di;

    const int o0 = lane * 4;
    const int o1 = (lane + 16) * 4;

    float4 bv0 = *(const float4*)(bias + o0);
    float4 bv1 = *(const float4*)(bias + o1);
    const float* hrow = g_h + (size_t)node * D;
    float4 hv0 = *(const float4*)(hrow + o0);
    float4 hv1 = *(const float4*)(hrow + o1);

    float4 a0, a1;
    a0.x = fmaf(hv0.x, d2, bv0.x);
    a0.y = fmaf(hv0.y, d2, bv0.y);
    a0.z = fmaf(hv0.z, d2, bv0.z);
    a0.w = fmaf(hv0.w, d2, bv0.w);
    a1.x = fmaf(hv1.x, d2, bv1.x);
    a1.y = fmaf(hv1.y, d2, bv1.y);
    a1.z = fmaf(hv1.z, d2, bv1.z);
    a1.w = fmaf(hv1.w, d2, bv1.w);

    int cnt = end - beg;
    if (cnt > 0) {
        const EdgeRec* ep = g_edges + beg;
        EdgeRec e0 = ep[0];
        EdgeRec e1 = (cnt > 1) ? ep[1] : e0;

        int i = 0;
        for (; i + 1 < cnt; i += 2) {
            const float* s0 = g_h + (size_t)e0.src * D;
            const float* s1 = g_h + (size_t)e1.src * D;
            float4 m00 = *(const float4*)(s0 + o0);
            float4 m01 = *(const float4*)(s0 + o1);
            float4 m10 = *(const float4*)(s1 + o0);
            float4 m11 = *(const float4*)(s1 + o1);
            float w0 = e0.w, w1 = e1.w;
            if (i + 2 < cnt) e0 = ep[i + 2];
            if (i + 3 < cnt) e1 = ep[i + 3];
            a0.x = fmaf(w0, m00.x, a0.x);
            a0.y = fmaf(w0, m00.y, a0.y);
            a0.z = fmaf(w0, m00.z, a0.z);
            a0.w = fmaf(w0, m00.w, a0.w);
            a1.x = fmaf(w0, m01.x, a1.x);
            a1.y = fmaf(w0, m01.y, a1.y);
            a1.z = fmaf(w0, m01.z, a1.z);
            a1.w = fmaf(w0, m01.w, a1.w);
            a0.x = fmaf(w1, m10.x, a0.x);
            a0.y = fmaf(w1, m10.y, a0.y);
            a0.z = fmaf(w1, m10.z, a0.z);
            a0.w = fmaf(w1, m10.w, a0.w);
            a1.x = fmaf(w1, m11.x, a1.x);
            a1.y = fmaf(w1, m11.y, a1.y);
            a1.z = fmaf(w1, m11.z, a1.z);
            a1.w = fmaf(w1, m11.w, a1.w);
        }
        if (i < cnt) {
            const float* s0 = g_h + (size_t)e0.src * D;
            float4 m00 = *(const float4*)(s0 + o0);
            float4 m01 = *(const float4*)(s0 + o1);
            a0.x = fmaf(e0.w, m00.x, a0.x);
            a0.y = fmaf(e0.w, m00.y, a0.y);
            a0.z = fmaf(e0.w, m00.z, a0.z);
            a0.w = fmaf(e0.w, m00.w, a0.w);
            a1.x = fmaf(e0.w, m01.x, a1.x);
            a1.y = fmaf(e0.w, m01.y, a1.y);
            a1.z = fmaf(e0.w, m01.z, a1.z);
            a1.w = fmaf(e0.w, m01.w, a1.w);
        }
    }

    float* orow = OUT + (size_t)node * D;
    *(float4*)(orow + o0) = a0;
    *(float4*)(orow + o1) = a1;
}

// ---------------------------------------------------------------------------
extern "C" void kernel_launch(void* const* d_in, const int* in_sizes, int n_in,
                              void* d_out, int out_size)
{
    const float* x  = (const float*)d_in[0];
    const void*  ei = d_in[1];               // int64 or int32, detected on device
    const float* W1 = (const float*)d_in[2];
    const float* b1 = (const float*)d_in[3];
    const float* W2 = (const float*)d_in[4];
    const float* b2 = (const float*)d_in[5];
    const float* W3 = (const float*)d_in[6];
    const float* b3 = (const float*)d_in[7];
    float* out = (float*)d_out;

    const int n = in_sizes[0] / D;       // 100000
    const int E = in_sizes[1] / 2;       // 640000
    const int T = 256;
    const int nb = (n + SCAN_B - 1) / SCAN_B;

    // ---- once per launch: dtype detect + dinv + CSR (5 launches) ----
    init_kernel<<<(n + T - 1) / T, T>>>(ei, n);
    count_deg_kernel<<<(E + T - 1) / T, T>>>(ei, E);
    scan_block_kernel<<<nb, SCAN_B>>>(n);     // also computes g_dinv
    finalize_rowptr_kernel<<<(n + T - 1) / T, T>>>(n, nb, E);
    fill_csr_kernel<<<(E + T - 1) / T, T>>>(ei, E);

    const int gemm_blocks = (n + TM - 1) / TM;
    const int agg_blocks = (int)(((long long)n * 16 + T - 1) / T);

    // layer 1: x -> g_a
    gemm_act_kernel<<<gemm_blocks, T>>>(x, 0, W1, n);
    aggregate_kernel<<<agg_blocks, T>>>(nullptr, 1, b1, n);

    // layer 2: g_a -> g_b
    gemm_act_kernel<<<gemm_blocks, T>>>(nullptr, 1, W2, n);
    aggregate_kernel<<<agg_blocks, T>>>(nullptr, 2, b2, n);

    // layer 3: g_b -> d_out
    gemm_act_kernel<<<gemm_blocks, T>>>(nullptr, 2, W3, n);
    aggregate_kernel<<<agg_blocks, T>>>(out, 0, b3, n);
}